// round 3
// baseline (speedup 1.0000x reference)
#include <cuda_runtime.h>

#define BM 128
#define BN 64
#define DH 128
#define NTHREADS 256
#define QT_STRIDE (BM + 4)   /* 132 floats, kk-major Q */
#define KT_STRIDE (BN + 4)   /* 68 floats,  kk-major K */
#define PS_STRIDE (BN + 4)   /* 68 floats,  row-major P */

__device__ __forceinline__ float ex2f(float x) {
    float y;
    asm("ex2.approx.ftz.f32 %0, %1;" : "=f"(y) : "f"(x));
    return y;
}

__global__ __launch_bounds__(NTHREADS, 1)
void sink_attn_kernel(const float* __restrict__ q,
                      const float* __restrict__ k,
                      const float* __restrict__ v,
                      const int* __restrict__ p_ns,
                      const int* __restrict__ p_ws,
                      float* __restrict__ out,
                      int N)
{
    extern __shared__ float smem[];
    float* Qt = smem;                       // DH * QT_STRIDE
    float* Kt = Qt + DH * QT_STRIDE;        // DH * KT_STRIDE
    float* Vs = Kt + DH * KT_STRIDE;        // BN * DH
    float* Ps = Vs + BN * DH;               // BM * PS_STRIDE

    const int ns = p_ns[0];
    const int ws = p_ws[0];

    // heavy blocks (large m0 -> most tiles) first
    const int m0 = (int)(gridDim.x - 1 - blockIdx.x) * BM;
    const size_t plane = (size_t)blockIdx.y * (size_t)N * DH;
    const float* qp = q + plane;
    const float* kp = k + plane;
    const float* vp = v + plane;
    float* op = out + plane;

    const int tid  = threadIdx.x;
    const int lane = tid & 31;
    const int warp = tid >> 5;
    const int tx   = tid & 15;   // S-col group / O-col group
    const int tyg  = tid >> 4;   // S/O row group (8 rows each)

    // fold softmax scale and log2(e) into Q so scores live in log2 domain
    const float qscale = 1.4426950408889634f * 0.08838834764831845f; // log2e / sqrt(128)

    // ---- load Q tile transposed (kk-major), pre-scaled ----
    {
        const int u = lane & 3, g = lane >> 2;
        #pragma unroll
        for (int half = 0; half < 2; half++) {
            const int row = half * 64 + warp * 8 + g;
            const float4* src = (const float4*)(qp + (size_t)(m0 + row) * DH);
            #pragma unroll
            for (int it = 0; it < 8; it++) {
                const int c4 = it * 4 + u;
                float4 val = src[c4];
                float* dst = Qt + (4 * c4) * QT_STRIDE + row;
                dst[0 * QT_STRIDE] = val.x * qscale;
                dst[1 * QT_STRIDE] = val.y * qscale;
                dst[2 * QT_STRIDE] = val.z * qscale;
                dst[3 * QT_STRIDE] = val.w * qscale;
            }
        }
    }

    float O[8][8];          // rows 8*tyg+i ; cols {4*tx..+3} and {64+4*tx..+3}
    float mrow[8], lrow[8];
    #pragma unroll
    for (int i = 0; i < 8; i++) {
        mrow[i] = -1e30f;
        lrow[i] = 0.0f;
        #pragma unroll
        for (int c = 0; c < 8; c++) O[i][c] = 0.0f;
    }

    // ---- tile schedule: window tiles + (optional) sink tiles ----
    // Window tiles must cover the window of the SMALLEST row in this block:
    // row m0 sees keys from m0 - ws + 1. (R1 bug: used m0 + BM - ws, dropping
    // up to BM-1 keys for every row but the last.)
    int n_lo = m0 - ws + 1;
    if (n_lo < 0) n_lo = 0;
    n_lo = (n_lo / BN) * BN;
    int n_sink_tiles = 0;
    if (n_lo > 0) {
        int t = (ns + BN - 1) / BN;
        int cap = n_lo / BN;
        n_sink_tiles = t < cap ? t : cap;
    }
    const int n_win_tiles = (m0 + BM - BN - n_lo) / BN + 1;
    const int n_tiles = n_sink_tiles + n_win_tiles;

    const int ibase  = m0 + 8 * tyg;
    const int jbase0 = 4 * tx;

    for (int t = 0; t < n_tiles; t++) {
        const int n0 = (t < n_sink_tiles) ? t * BN
                                          : n_lo + (t - n_sink_tiles) * BN;

        __syncthreads();   // previous PV done before overwriting Kt/Vs

        // load K tile transposed (kk-major)
        {
            const int u = lane & 3, g = lane >> 2;
            const int row = warp * 8 + g;
            const float4* src = (const float4*)(kp + (size_t)(n0 + row) * DH);
            #pragma unroll
            for (int it = 0; it < 8; it++) {
                const int c4 = it * 4 + u;
                float4 val = src[c4];
                float* dst = Kt + (4 * c4) * KT_STRIDE + row;
                dst[0 * KT_STRIDE] = val.x;
                dst[1 * KT_STRIDE] = val.y;
                dst[2 * KT_STRIDE] = val.z;
                dst[3 * KT_STRIDE] = val.w;
            }
        }
        // load V tile (row-major)
        {
            const float4* src = (const float4*)(vp + (size_t)n0 * DH);
            float4* dst = (float4*)Vs;
            #pragma unroll
            for (int it = 0; it < 8; it++) {
                const int f4 = it * NTHREADS + tid;
                dst[f4] = src[f4];
            }
        }
        __syncthreads();

        // ---- S = Q K^T (log2 domain) ----
        float s[8][4];
        #pragma unroll
        for (int i = 0; i < 8; i++)
            #pragma unroll
            for (int j = 0; j < 4; j++) s[i][j] = 0.0f;

        #pragma unroll 2
        for (int kk = 0; kk < DH; kk++) {
            const float4* qrow = (const float4*)(Qt + kk * QT_STRIDE);
            const float4* krow = (const float4*)(Kt + kk * KT_STRIDE);
            float4 q0 = qrow[2 * tyg];
            float4 q1 = qrow[2 * tyg + 1];
            float4 kv = krow[tx];
            float qr[8] = {q0.x, q0.y, q0.z, q0.w, q1.x, q1.y, q1.z, q1.w};
            float kr[4] = {kv.x, kv.y, kv.z, kv.w};
            #pragma unroll
            for (int i = 0; i < 8; i++)
                #pragma unroll
                for (int j = 0; j < 4; j++)
                    s[i][j] += qr[i] * kr[j];
        }

        // ---- mask + online softmax ----
        const int jb = n0 + jbase0;
        #pragma unroll
        for (int i = 0; i < 8; i++) {
            const int ig = ibase + i;
            #pragma unroll
            for (int j = 0; j < 4; j++) {
                const int jg = jb + j;
                const bool valid = (jg <= ig) && ((jg < ns) | ((ig - jg) < ws));
                if (!valid) s[i][j] = -1e30f;
            }
            float tm = fmaxf(fmaxf(s[i][0], s[i][1]), fmaxf(s[i][2], s[i][3]));
            #pragma unroll
            for (int off = 8; off > 0; off >>= 1)
                tm = fmaxf(tm, __shfl_xor_sync(0xffffffffu, tm, off));
            const float mnew = fmaxf(mrow[i], tm);
            const float alpha = ex2f(mrow[i] - mnew);
            mrow[i] = mnew;
            float rs = 0.0f;
            #pragma unroll
            for (int j = 0; j < 4; j++) {
                const float p = ex2f(s[i][j] - mnew);
                s[i][j] = p;
                rs += p;
            }
            #pragma unroll
            for (int off = 8; off > 0; off >>= 1)
                rs += __shfl_xor_sync(0xffffffffu, rs, off);
            lrow[i] = lrow[i] * alpha + rs;
            #pragma unroll
            for (int c = 0; c < 8; c++) O[i][c] *= alpha;
            ((float4*)(Ps + (8 * tyg + i) * PS_STRIDE))[tx] =
                make_float4(s[i][0], s[i][1], s[i][2], s[i][3]);
        }
        __syncthreads();

        // ---- O += P V ----
        #pragma unroll 2
        for (int j = 0; j < BN; j++) {
            const float4* vrow = (const float4*)(Vs + j * DH);
            const float4 v0 = vrow[tx];
            const float4 v1 = vrow[16 + tx];
            float pr[8];
            #pragma unroll
            for (int i = 0; i < 8; i++)
                pr[i] = Ps[(8 * tyg + i) * PS_STRIDE + j];
            #pragma unroll
            for (int i = 0; i < 8; i++) {
                O[i][0] += pr[i] * v0.x;
                O[i][1] += pr[i] * v0.y;
                O[i][2] += pr[i] * v0.z;
                O[i][3] += pr[i] * v0.w;
                O[i][4] += pr[i] * v1.x;
                O[i][5] += pr[i] * v1.y;
                O[i][6] += pr[i] * v1.z;
                O[i][7] += pr[i] * v1.w;
            }
        }
    }

    // ---- epilogue: normalize and store ----
    #pragma unroll
    for (int i = 0; i < 8; i++) {
        const float linv = 1.0f / lrow[i];
        float* orow = op + (size_t)(ibase + i) * DH;
        ((float4*)orow)[tx] =
            make_float4(O[i][0] * linv, O[i][1] * linv, O[i][2] * linv, O[i][3] * linv);
        ((float4*)orow)[16 + tx] =
            make_float4(O[i][4] * linv, O[i][5] * linv, O[i][6] * linv, O[i][7] * linv);
    }
}

extern "C" void kernel_launch(void* const* d_in, const int* in_sizes, int n_in,
                              void* d_out, int out_size) {
    const float* q = (const float*)d_in[0];
    const float* k = (const float*)d_in[1];
    const float* v = (const float*)d_in[2];
    const int* ns  = (const int*)d_in[3];
    const int* ws  = (const int*)d_in[4];
    float* out = (float*)d_out;

    const int N = 2048;
    const int BH = in_sizes[0] / (N * DH);   // B*H = 32

    const size_t smem_bytes =
        (size_t)(DH * QT_STRIDE + DH * KT_STRIDE + BN * DH + BM * PS_STRIDE) * sizeof(float);
    cudaFuncSetAttribute(sink_attn_kernel,
                         cudaFuncAttributeMaxDynamicSharedMemorySize, (int)smem_bytes);

    dim3 grid(N / BM, BH);
    sink_attn_kernel<<<grid, NTHREADS, smem_bytes>>>(q, k, v, ns, ws, out, N);
}

// round 12
// speedup vs baseline: 4.3903x; 4.3903x over previous
#include <cuda_runtime.h>
#include <cuda_bf16.h>
#include <cstdint>

#define BM 128
#define BN 64
#define DH 128
#define NTH 256

// ---- one smem pool for both bodies ----
#define OFF_QH 1024
#define OFF_QL (OFF_QH + 32768)
#define OFF_K  (OFF_QL + 32768)   /* + buf*32768, lo half at +16384 */
#define OFF_V  (OFF_K + 65536)    /* + buf*32768, lo half at +16384 */
#define SMEM_TOTAL (OFF_V + 65536)   /* 197632 B; SIMT needs 169984 B */

// SIMT strides (floats)
#define QT_STRIDE (BM + 4)
#define KT_STRIDE (BN + 4)
#define PS_STRIDE (BN + 4)

// TMEM columns
#define TM_O   0
#define TM_S   128
#define TM_PH  192
#define TM_PL  224
#define TMEM_COLS 256

#define IDESC_QK 0x8100490u   /* f16-kind, F32 acc, BF16xBF16, M=128 N=64  */
#define IDESC_PV 0x8200490u   /* M=128 N=128 */

#define SWZ(x) ((x) ^ (((x) >> 3) & 0x70))

#if defined(__CUDA_ARCH_FEAT_SM103_ALL) || defined(__CUDA_ARCH_FEAT_SM100_ALL) || \
    (defined(__CUDA_ARCH_SPECIFIC__) && (__CUDA_ARCH_SPECIFIC__ >= 1000)) || \
    (defined(__CUDA_ARCH_FAMILY_SPECIFIC__) && (__CUDA_ARCH_FAMILY_SPECIFIC__ >= 1000))
#define HAS_TCGEN05 1
#else
#define HAS_TCGEN05 0
#endif

__device__ __forceinline__ float ex2f(float x) {
    float y; asm("ex2.approx.ftz.f32 %0, %1;" : "=f"(y) : "f"(x)); return y;
}

#if HAS_TCGEN05
// ======================= tcgen05 machinery =======================
static constexpr uint64_t DESC_BASE =
    (2ull << 61) | (1ull << 46) | (64ull << 32) | (1ull << 16); // SW128, LBO=1, SBO=64
__device__ __forceinline__ uint64_t mk_desc(uint32_t a) {
    return DESC_BASE | ((uint64_t)(a >> 4) & 0x3FFF);
}
__device__ __forceinline__ uint32_t smem_u32(const void* p) {
    uint32_t a;
    asm("{ .reg .u64 t; cvta.to.shared.u64 t, %1; cvt.u32.u64 %0, t; }" : "=r"(a) : "l"(p));
    return a;
}
__device__ __forceinline__ uint32_t elect_one() {
    uint32_t pr;
    asm volatile("{\n\t.reg .pred p;\n\telect.sync _|p, 0xFFFFFFFF;\n\tselp.b32 %0, 1, 0, p;\n\t}" : "=r"(pr));
    return pr;
}
__device__ __forceinline__ uint32_t pack2(float a, float b) {  // lo=a, hi=b
    uint32_t r; asm("cvt.rn.bf16x2.f32 %0, %1, %2;" : "=r"(r) : "f"(b), "f"(a)); return r;
}
__device__ __forceinline__ float lo_f(uint32_t u) { return __uint_as_float(u << 16); }
__device__ __forceinline__ float hi_f(uint32_t u) { return __uint_as_float(u & 0xffff0000u); }

#define MBAR_INIT(a, c) asm volatile("mbarrier.init.shared.b64 [%0], %1;" :: "r"(a), "r"(c) : "memory")

// Bounded wait: a protocol hang degrades to wrong-output + termination
// (diagnosable rel_err) instead of a container timeout. 1<<22 attempts
// (~0.2s) is >>1e5x any legitimate wait in this kernel.
__device__ __forceinline__ void mbar_wait(uint32_t a, uint32_t ph) {
    for (int i = 0; i < (1 << 22); i++) {
        uint32_t done;
        asm volatile("{\n\t.reg .pred P;\n\t"
            "mbarrier.try_wait.parity.acquire.cta.shared::cta.b64 P, [%1], %2, 0x989680;\n\t"
            "selp.b32 %0, 1, 0, P;\n\t}"
            : "=r"(done) : "r"(a), "r"(ph) : "memory");
        if (done) return;
    }
}

#define TC_ALLOC(sa, n)   asm volatile("tcgen05.alloc.cta_group::1.sync.aligned.shared::cta.b32 [%0], %1;" :: "r"(sa), "r"(n) : "memory")
#define TC_DEALLOC(tb, n) asm volatile("tcgen05.dealloc.cta_group::1.sync.aligned.b32 %0, %1;" :: "r"(tb), "r"(n))
#define TC_RELINQ()       asm volatile("tcgen05.relinquish_alloc_permit.cta_group::1.sync.aligned;")
#define TC_COMMIT(a)      asm volatile("tcgen05.commit.cta_group::1.mbarrier::arrive::one.shared::cluster.b64 [%0];" :: "r"(a) : "memory")
#define TC_WAIT_LD()      asm volatile("tcgen05.wait::ld.sync.aligned;" ::: "memory")
#define TC_WAIT_ST()      asm volatile("tcgen05.wait::st.sync.aligned;" ::: "memory")
#define TC_FENCE_BEFORE() asm volatile("tcgen05.fence::before_thread_sync;" ::: "memory")
#define TC_FENCE_AFTER()  asm volatile("tcgen05.fence::after_thread_sync;" ::: "memory")
#define FENCE_ASYNC()     asm volatile("fence.proxy.async.shared::cta;" ::: "memory")

#define TC_LD_X32(r, ta) \
    asm volatile("tcgen05.ld.sync.aligned.32x32b.x32.b32 " \
        "{%0,%1,%2,%3,%4,%5,%6,%7,%8,%9,%10,%11,%12,%13,%14,%15," \
        "%16,%17,%18,%19,%20,%21,%22,%23,%24,%25,%26,%27,%28,%29,%30,%31}, [%32];" \
        : "=r"((r)[0]),"=r"((r)[1]),"=r"((r)[2]),"=r"((r)[3]),"=r"((r)[4]),"=r"((r)[5]),"=r"((r)[6]),"=r"((r)[7]), \
          "=r"((r)[8]),"=r"((r)[9]),"=r"((r)[10]),"=r"((r)[11]),"=r"((r)[12]),"=r"((r)[13]),"=r"((r)[14]),"=r"((r)[15]), \
          "=r"((r)[16]),"=r"((r)[17]),"=r"((r)[18]),"=r"((r)[19]),"=r"((r)[20]),"=r"((r)[21]),"=r"((r)[22]),"=r"((r)[23]), \
          "=r"((r)[24]),"=r"((r)[25]),"=r"((r)[26]),"=r"((r)[27]),"=r"((r)[28]),"=r"((r)[29]),"=r"((r)[30]),"=r"((r)[31]) \
        : "r"(ta))

#define TC_ST_X16(ta, r) \
    asm volatile("tcgen05.st.sync.aligned.32x32b.x16.b32 [%0], " \
        "{%1,%2,%3,%4,%5,%6,%7,%8,%9,%10,%11,%12,%13,%14,%15,%16};" \
        :: "r"(ta), \
           "r"((r)[0]),"r"((r)[1]),"r"((r)[2]),"r"((r)[3]),"r"((r)[4]),"r"((r)[5]),"r"((r)[6]),"r"((r)[7]), \
           "r"((r)[8]),"r"((r)[9]),"r"((r)[10]),"r"((r)[11]),"r"((r)[12]),"r"((r)[13]),"r"((r)[14]),"r"((r)[15]) \
        : "memory")

__device__ __forceinline__ void mma_ss(uint32_t d, uint64_t a, uint64_t b, uint32_t idesc, uint32_t en) {
    asm volatile("{\n\t.reg .pred p;\n\tsetp.ne.u32 p, %5, 0;\n\t"
        "tcgen05.mma.cta_group::1.kind::f16 [%0], %1, %2, %3, {%4,%4,%4,%4}, p;\n\t}"
        :: "r"(d), "l"(a), "l"(b), "r"(idesc), "r"(0u), "r"(en) : "memory");
}
__device__ __forceinline__ void mma_ts(uint32_t d, uint32_t a, uint64_t b, uint32_t idesc, uint32_t en) {
    asm volatile("{\n\t.reg .pred p;\n\tsetp.ne.u32 p, %5, 0;\n\t"
        "tcgen05.mma.cta_group::1.kind::f16 [%0], [%1], %2, %3, {%4,%4,%4,%4}, p;\n\t}"
        :: "r"(d), "r"(a), "l"(b), "r"(idesc), "r"(0u), "r"(en) : "memory");
}

// blocked-atom SW128 byte offsets (pre-swizzle)
__device__ __forceinline__ uint32_t q_off(int r, int d) { return (uint32_t)(((r >> 3) + (d >> 6) * 16) * 1024 + (r & 7) * 128 + (d & 63) * 2); }
__device__ __forceinline__ uint32_t k_off(int j, int d) { return (uint32_t)(((j >> 3) + (d >> 6) * 8)  * 1024 + (j & 7) * 128 + (d & 63) * 2); }
__device__ __forceinline__ uint32_t v_off(int d, int j) { return (uint32_t)((d >> 3) * 1024 + (d & 7) * 128 + j * 2); }

__device__ __forceinline__ void load_kv(const float* kp, const float* vp, int n0,
                                        char* smem, int buf, int tid2)
{
    const int lane = tid2 & 31, wq = tid2 >> 5;
    char* kh = smem + OFF_K + buf * 32768;
    char* kl = kh + 16384;
    #pragma unroll 4
    for (int it = 0; it < 16; it++) {
        const int j = it * 4 + wq;
        const float4 x = *(const float4*)(kp + (size_t)(n0 + j) * DH + lane * 4);
        const uint32_t h01 = pack2(x.x, x.y), h23 = pack2(x.z, x.w);
        const uint32_t l01 = pack2(x.x - lo_f(h01), x.y - hi_f(h01));
        const uint32_t l23 = pack2(x.z - lo_f(h23), x.w - hi_f(h23));
        const uint32_t off = SWZ(k_off(j, lane * 4));
        *(uint2*)(kh + off) = make_uint2(h01, h23);
        *(uint2*)(kl + off) = make_uint2(l01, l23);
    }
    char* vh = smem + OFF_V + buf * 32768;
    char* vl = vh + 16384;
    const float* va = vp + (size_t)(n0 + 2 * lane) * DH;
    const float* vb = va + DH;
    #pragma unroll 2
    for (int dg = 0; dg < 8; dg++) {
        const int d0 = wq * 32 + dg * 4;
        const float4 a = *(const float4*)(va + d0);
        const float4 b = *(const float4*)(vb + d0);
        const float av[4] = {a.x, a.y, a.z, a.w}, bv[4] = {b.x, b.y, b.z, b.w};
        #pragma unroll
        for (int i = 0; i < 4; i++) {
            const uint32_t h = pack2(av[i], bv[i]);
            const uint32_t l = pack2(av[i] - lo_f(h), bv[i] - hi_f(h));
            const uint32_t off = SWZ(v_off(d0 + i, 2 * lane));
            *(uint32_t*)(vh + off) = h;
            *(uint32_t*)(vl + off) = l;
        }
    }
}

__device__ __forceinline__ void issue_qk(uint32_t sb, uint32_t tb, int buf) {
    const uint32_t d = tb + TM_S;
    const uint64_t qh = mk_desc(sb + OFF_QH), ql = mk_desc(sb + OFF_QL);
    const uint64_t kh = mk_desc(sb + OFF_K + buf * 32768), kl = kh + 1024;
    const uint64_t aa[3] = {qh, qh, ql};
    const uint64_t bb[3] = {kh, kl, kh};
    #pragma unroll
    for (int term = 0; term < 3; term++)
        #pragma unroll
        for (int s = 0; s < 8; s++)
            mma_ss(d, aa[term] + (s >> 2) * 1024 + (s & 3) * 2,
                      bb[term] + (s >> 2) * 512  + (s & 3) * 2,
                   IDESC_QK, (term == 0 && s == 0) ? 0u : 1u);
}
__device__ __forceinline__ void issue_pv(uint32_t sb, uint32_t tb, int buf, int first) {
    const uint32_t d = tb + TM_O;
    const uint64_t vh = mk_desc(sb + OFF_V + buf * 32768), vl = vh + 1024;
    const uint32_t pa[3] = {tb + TM_PH, tb + TM_PH, tb + TM_PL};
    const uint64_t bb[3] = {vh, vl, vh};
    #pragma unroll
    for (int term = 0; term < 3; term++)
        #pragma unroll
        for (int s = 0; s < 4; s++)
            mma_ts(d, pa[term] + s * 8, bb[term] + s * 2,
                   IDESC_PV, (first && term == 0 && s == 0) ? 0u : 1u);
}
#endif  // HAS_TCGEN05

__global__ __launch_bounds__(NTH, 1)
void sink_attn(const float* __restrict__ q, const float* __restrict__ k,
               const float* __restrict__ v, const int* __restrict__ p_ns,
               const int* __restrict__ p_ws, float* __restrict__ out, int N)
{
    extern __shared__ char smem_raw[];
    const int ns = p_ns[0], ws = p_ws[0];
    const int m0 = (int)(gridDim.x - 1 - blockIdx.x) * BM;
    const size_t plane = (size_t)blockIdx.y * (size_t)N * DH;
    const float* qp = q + plane;
    const float* kp = k + plane;
    const float* vp = v + plane;
    float* op = out + plane;
    const int tid = threadIdx.x, lane = tid & 31, wid = tid >> 5;

    // tile schedule: window must cover row m0 (keys from m0-ws+1)
    int n_lo = m0 - ws + 1;
    if (n_lo < 0) n_lo = 0;
    n_lo = (n_lo / BN) * BN;
    int n_sink = 0;
    if (n_lo > 0) {
        int t = (ns + BN - 1) / BN, cap = n_lo / BN;
        n_sink = t < cap ? t : cap;
    }
    const int n_tiles = n_sink + (m0 + BM - BN - n_lo) / BN + 1;
    const float qscale = 1.4426950408889634f * 0.08838834764831845f; // log2e/sqrt(128)

#if HAS_TCGEN05
    // ================= tcgen05 body =================
    char* smem = smem_raw;
    const uint32_t sb = smem_u32(smem);

    if (wid == 0) { TC_ALLOC(sb, TMEM_COLS); TC_RELINQ(); }
    if (tid == 0) MBAR_INIT(sb + 16, 1);
    __syncthreads();
    uint32_t tb;
    asm volatile("ld.shared.b32 %0, [%1];" : "=r"(tb) : "r"(sb));

    // prologue: WG0 preps Q hi/lo; WG1 loads K/V tile 0
    if (tid < 128) {
        #pragma unroll 4
        for (int it = 0; it < 32; it++) {
            const int j = it * 4 + wid;
            float4 x = *(const float4*)(qp + (size_t)(m0 + j) * DH + lane * 4);
            x.x *= qscale; x.y *= qscale; x.z *= qscale; x.w *= qscale;
            const uint32_t h01 = pack2(x.x, x.y), h23 = pack2(x.z, x.w);
            const uint32_t l01 = pack2(x.x - lo_f(h01), x.y - hi_f(h01));
            const uint32_t l23 = pack2(x.z - lo_f(h23), x.w - hi_f(h23));
            const uint32_t off = SWZ(q_off(j, lane * 4));
            *(uint2*)(smem + OFF_QH + off) = make_uint2(h01, h23);
            *(uint2*)(smem + OFF_QL + off) = make_uint2(l01, l23);
        }
    } else {
        const int n0 = (0 < n_sink) ? 0 : n_lo;
        load_kv(kp, vp, n0, smem, 0, tid - 128);
    }
    FENCE_ASYNC();
    __syncthreads();

    if (wid == 0) {
        TC_FENCE_AFTER();
        if (elect_one()) { issue_qk(sb, tb, 0); TC_COMMIT(sb + 16); }
    }

    float lsum = 0.0f;
    for (int t = 0; t < n_tiles; t++) {
        const int n0 = (t < n_sink) ? t * BN : n_lo + (t - n_sink) * BN;
        const int buf = t & 1;

        mbar_wait(sb + 16, t & 1);   // S(t) ready; PV(t-1) done
        TC_FENCE_AFTER();

        if (tid < 128) {
            const int ig = m0 + wid * 32 + lane;
            const uint32_t woff = (uint32_t)wid << 21;
            #pragma unroll
            for (int c = 0; c < 2; c++) {
                uint32_t sr[32];
                TC_LD_X32(sr, tb + TM_S + c * 32);
                TC_WAIT_LD();
                const int jb = n0 + c * 32;
                uint32_t ph[16], pl[16];
                float acc = 0.0f;
                #pragma unroll
                for (int kk = 0; kk < 32; kk += 2) {
                    const int j0 = jb + kk, j1 = j0 + 1;
                    float x0 = __uint_as_float(sr[kk]);
                    float x1 = __uint_as_float(sr[kk + 1]);
                    if (!((j0 <= ig) && ((j0 < ns) | ((ig - j0) < ws)))) x0 = -126.0f;
                    if (!((j1 <= ig) && ((j1 < ns) | ((ig - j1) < ws)))) x1 = -126.0f;
                    const float p0 = ex2f(x0), p1 = ex2f(x1);
                    acc += p0 + p1;
                    const uint32_t h = pack2(p0, p1);
                    ph[kk >> 1] = h;
                    pl[kk >> 1] = pack2(p0 - lo_f(h), p1 - hi_f(h));
                }
                lsum += acc;
                TC_ST_X16(tb + TM_PH + c * 16 + woff, ph);
                TC_ST_X16(tb + TM_PL + c * 16 + woff, pl);
            }
            TC_WAIT_ST();
            TC_FENCE_BEFORE();
        } else if (t + 1 < n_tiles) {
            const int t1 = t + 1;
            const int n1 = (t1 < n_sink) ? t1 * BN : n_lo + (t1 - n_sink) * BN;
            load_kv(kp, vp, n1, smem, t1 & 1, tid - 128);
            FENCE_ASYNC();
        }
        __syncthreads();

        if (wid == 0) {
            TC_FENCE_AFTER();
            if (elect_one()) {
                issue_pv(sb, tb, buf, t == 0);
                if (t + 1 < n_tiles) issue_qk(sb, tb, (t + 1) & 1);
                TC_COMMIT(sb + 16);
            }
        }
    }

    mbar_wait(sb + 16, n_tiles & 1);   // final PV done
    TC_FENCE_AFTER();

    if (tid < 128) {
        const float inv = 1.0f / lsum;
        float* orow = op + (size_t)(m0 + wid * 32 + lane) * DH;
        #pragma unroll
        for (int c = 0; c < 4; c++) {
            uint32_t orr[32];
            TC_LD_X32(orr, tb + TM_O + c * 32);
            TC_WAIT_LD();
            float4* dst = (float4*)(orow + c * 32);
            #pragma unroll
            for (int g = 0; g < 8; g++)
                dst[g] = make_float4(__uint_as_float(orr[4 * g + 0]) * inv,
                                     __uint_as_float(orr[4 * g + 1]) * inv,
                                     __uint_as_float(orr[4 * g + 2]) * inv,
                                     __uint_as_float(orr[4 * g + 3]) * inv);
        }
        TC_FENCE_BEFORE();
    }
    __syncthreads();
    if (wid == 0) TC_DEALLOC(tb, TMEM_COLS);

#else
    // ================= SIMT fallback (proven R3 body) =================
    float* smemf = (float*)smem_raw;
    float* Qt = smemf;
    float* Kt = Qt + DH * QT_STRIDE;
    float* Vs = Kt + DH * KT_STRIDE;
    float* Ps = Vs + BN * DH;

    const int warp = wid;
    const int tx  = tid & 15;
    const int tyg = tid >> 4;

    {
        const int u = lane & 3, g = lane >> 2;
        #pragma unroll
        for (int half = 0; half < 2; half++) {
            const int row = half * 64 + warp * 8 + g;
            const float4* src = (const float4*)(qp + (size_t)(m0 + row) * DH);
            #pragma unroll
            for (int it = 0; it < 8; it++) {
                const int c4 = it * 4 + u;
                float4 val = src[c4];
                float* dst = Qt + (4 * c4) * QT_STRIDE + row;
                dst[0 * QT_STRIDE] = val.x * qscale;
                dst[1 * QT_STRIDE] = val.y * qscale;
                dst[2 * QT_STRIDE] = val.z * qscale;
                dst[3 * QT_STRIDE] = val.w * qscale;
            }
        }
    }

    float O[8][8], mrow[8], lrow[8];
    #pragma unroll
    for (int i = 0; i < 8; i++) {
        mrow[i] = -1e30f; lrow[i] = 0.0f;
        #pragma unroll
        for (int c = 0; c < 8; c++) O[i][c] = 0.0f;
    }

    const int ibase = m0 + 8 * tyg;
    const int jbase0 = 4 * tx;

    for (int t = 0; t < n_tiles; t++) {
        const int n0 = (t < n_sink) ? t * BN : n_lo + (t - n_sink) * BN;
        __syncthreads();
        {
            const int u = lane & 3, g = lane >> 2;
            const int row = warp * 8 + g;
            const float4* src = (const float4*)(kp + (size_t)(n0 + row) * DH);
            #pragma unroll
            for (int it = 0; it < 8; it++) {
                const int c4 = it * 4 + u;
                float4 val = src[c4];
                float* dst = Kt + (4 * c4) * KT_STRIDE + row;
                dst[0 * KT_STRIDE] = val.x;
                dst[1 * KT_STRIDE] = val.y;
                dst[2 * KT_STRIDE] = val.z;
                dst[3 * KT_STRIDE] = val.w;
            }
        }
        {
            const float4* src = (const float4*)(vp + (size_t)n0 * DH);
            float4* dst = (float4*)Vs;
            #pragma unroll
            for (int it = 0; it < 8; it++) dst[it * NTH + tid] = src[it * NTH + tid];
        }
        __syncthreads();

        float s[8][4];
        #pragma unroll
        for (int i = 0; i < 8; i++)
            #pragma unroll
            for (int j = 0; j < 4; j++) s[i][j] = 0.0f;

        #pragma unroll 2
        for (int kk = 0; kk < DH; kk++) {
            const float4* qrow = (const float4*)(Qt + kk * QT_STRIDE);
            const float4* krow = (const float4*)(Kt + kk * KT_STRIDE);
            float4 q0 = qrow[2 * tyg], q1 = qrow[2 * tyg + 1], kv = krow[tx];
            float qr[8] = {q0.x, q0.y, q0.z, q0.w, q1.x, q1.y, q1.z, q1.w};
            float kr[4] = {kv.x, kv.y, kv.z, kv.w};
            #pragma unroll
            for (int i = 0; i < 8; i++)
                #pragma unroll
                for (int j = 0; j < 4; j++) s[i][j] += qr[i] * kr[j];
        }

        const int jb = n0 + jbase0;
        #pragma unroll
        for (int i = 0; i < 8; i++) {
            const int ig = ibase + i;
            #pragma unroll
            for (int j = 0; j < 4; j++) {
                const int jg = jb + j;
                if (!((jg <= ig) && ((jg < ns) | ((ig - jg) < ws)))) s[i][j] = -1e30f;
            }
            float tm = fmaxf(fmaxf(s[i][0], s[i][1]), fmaxf(s[i][2], s[i][3]));
            #pragma unroll
            for (int off = 8; off > 0; off >>= 1)
                tm = fmaxf(tm, __shfl_xor_sync(0xffffffffu, tm, off));
            const float mnew = fmaxf(mrow[i], tm);
            const float alpha = ex2f(mrow[i] - mnew);
            mrow[i] = mnew;
            float rs = 0.0f;
            #pragma unroll
            for (int j = 0; j < 4; j++) { const float p = ex2f(s[i][j] - mnew); s[i][j] = p; rs += p; }
            #pragma unroll
            for (int off = 8; off > 0; off >>= 1)
                rs += __shfl_xor_sync(0xffffffffu, rs, off);
            lrow[i] = lrow[i] * alpha + rs;
            #pragma unroll
            for (int c = 0; c < 8; c++) O[i][c] *= alpha;
            ((float4*)(Ps + (8 * tyg + i) * PS_STRIDE))[tx] =
                make_float4(s[i][0], s[i][1], s[i][2], s[i][3]);
        }
        __syncthreads();

        #pragma unroll 2
        for (int j = 0; j < BN; j++) {
            const float4* vrow = (const float4*)(Vs + j * DH);
            const float4 v0 = vrow[tx], v1 = vrow[16 + tx];
            float pr[8];
            #pragma unroll
            for (int i = 0; i < 8; i++) pr[i] = Ps[(8 * tyg + i) * PS_STRIDE + j];
            #pragma unroll
            for (int i = 0; i < 8; i++) {
                O[i][0] += pr[i] * v0.x; O[i][1] += pr[i] * v0.y;
                O[i][2] += pr[i] * v0.z; O[i][3] += pr[i] * v0.w;
                O[i][4] += pr[i] * v1.x; O[i][5] += pr[i] * v1.y;
                O[i][6] += pr[i] * v1.z; O[i][7] += pr[i] * v1.w;
            }
        }
    }

    #pragma unroll
    for (int i = 0; i < 8; i++) {
        const float linv = 1.0f / lrow[i];
        float* orow = op + (size_t)(ibase + i) * DH;
        ((float4*)orow)[tx] = make_float4(O[i][0]*linv, O[i][1]*linv, O[i][2]*linv, O[i][3]*linv);
        ((float4*)orow)[16 + tx] = make_float4(O[i][4]*linv, O[i][5]*linv, O[i][6]*linv, O[i][7]*linv);
    }
#endif
}

extern "C" void kernel_launch(void* const* d_in, const int* in_sizes, int n_in,
                              void* d_out, int out_size) {
    const float* q = (const float*)d_in[0];
    const float* k = (const float*)d_in[1];
    const float* v = (const float*)d_in[2];
    const int* ns  = (const int*)d_in[3];
    const int* ws  = (const int*)d_in[4];
    float* out = (float*)d_out;

    const int N = 2048;
    const int BH = in_sizes[0] / (N * DH);

    cudaFuncSetAttribute(sink_attn,
                         cudaFuncAttributeMaxDynamicSharedMemorySize, SMEM_TOTAL);
    dim3 grid(N / BM, BH);
    sink_attn<<<grid, NTH, SMEM_TOTAL>>>(q, k, v, ns, ws, out, N);
}

// round 14
// speedup vs baseline: 4.9607x; 1.1299x over previous
#include <cuda_runtime.h>
#include <cuda_bf16.h>
#include <cstdint>

#define BM 128
#define BN 64
#define DH 128
#define NTH 256

// ---- smem pool (shared by both bodies) ----
#define OFF_QH 1024
#define OFF_QL (OFF_QH + 32768)
#define OFF_K  (OFF_QL + 32768)   /* + buf*32768, lo half at +16384 */
#define OFF_V  (OFF_K + 65536)    /* + buf*32768, lo half at +16384 */
#define SMEM_TOTAL (OFF_V + 65536)

// SIMT strides (floats)
#define QT_STRIDE (BM + 4)
#define KT_STRIDE (BN + 4)
#define PS_STRIDE (BN + 4)

// TMEM columns: O[0,128) | S0[128,192) S1[192,256) | P0 h/l [256,320) P1 h/l [320,384)
#define TM_O   0
#define TM_S0  128
#define TM_P0  256
#define TMEM_COLS 512

#define IDESC_QK 0x8100490u   /* f16-kind, F32 acc, BF16xBF16, M=128 N=64  */
#define IDESC_PV 0x8200490u   /* M=128 N=128 */

#define SWZ(x) ((x) ^ (((x) >> 3) & 0x70))

#if defined(__CUDA_ARCH_FEAT_SM103_ALL) || defined(__CUDA_ARCH_FEAT_SM100_ALL) || \
    (defined(__CUDA_ARCH_SPECIFIC__) && (__CUDA_ARCH_SPECIFIC__ >= 1000)) || \
    (defined(__CUDA_ARCH_FAMILY_SPECIFIC__) && (__CUDA_ARCH_FAMILY_SPECIFIC__ >= 1000))
#define HAS_TCGEN05 1
#else
#define HAS_TCGEN05 0
#endif

__device__ __forceinline__ float ex2f(float x) {
    float y; asm("ex2.approx.ftz.f32 %0, %1;" : "=f"(y) : "f"(x)); return y;
}

#if HAS_TCGEN05
// ======================= tcgen05 machinery =======================
static constexpr uint64_t DESC_BASE =
    (2ull << 61) | (1ull << 46) | (64ull << 32) | (1ull << 16); // SW128, LBO=1, SBO=64
__device__ __forceinline__ uint64_t mk_desc(uint32_t a) {
    return DESC_BASE | ((uint64_t)(a >> 4) & 0x3FFF);
}
__device__ __forceinline__ uint32_t smem_u32(const void* p) {
    uint32_t a;
    asm("{ .reg .u64 t; cvta.to.shared.u64 t, %1; cvt.u32.u64 %0, t; }" : "=r"(a) : "l"(p));
    return a;
}
__device__ __forceinline__ uint32_t elect_one() {
    uint32_t pr;
    asm volatile("{\n\t.reg .pred p;\n\telect.sync _|p, 0xFFFFFFFF;\n\tselp.b32 %0, 1, 0, p;\n\t}" : "=r"(pr));
    return pr;
}
__device__ __forceinline__ uint32_t pack2(float a, float b) {  // lo=a, hi=b
    uint32_t r; asm("cvt.rn.bf16x2.f32 %0, %1, %2;" : "=r"(r) : "f"(b), "f"(a)); return r;
}
__device__ __forceinline__ float lo_f(uint32_t u) { return __uint_as_float(u << 16); }
__device__ __forceinline__ float hi_f(uint32_t u) { return __uint_as_float(u & 0xffff0000u); }

#define MBAR_INIT(a, c) asm volatile("mbarrier.init.shared.b64 [%0], %1;" :: "r"(a), "r"(c) : "memory")

// Bounded wait: a protocol hang degrades to wrong-output (diagnosable) not timeout.
__device__ __forceinline__ void mbar_wait(uint32_t a, uint32_t ph) {
    for (int i = 0; i < (1 << 22); i++) {
        uint32_t done;
        asm volatile("{\n\t.reg .pred P;\n\t"
            "mbarrier.try_wait.parity.acquire.cta.shared::cta.b64 P, [%1], %2, 0x989680;\n\t"
            "selp.b32 %0, 1, 0, P;\n\t}"
            : "=r"(done) : "r"(a), "r"(ph) : "memory");
        if (done) return;
    }
}

#define TC_ALLOC(sa, n)   asm volatile("tcgen05.alloc.cta_group::1.sync.aligned.shared::cta.b32 [%0], %1;" :: "r"(sa), "r"(n) : "memory")
#define TC_DEALLOC(tb, n) asm volatile("tcgen05.dealloc.cta_group::1.sync.aligned.b32 %0, %1;" :: "r"(tb), "r"(n))
#define TC_RELINQ()       asm volatile("tcgen05.relinquish_alloc_permit.cta_group::1.sync.aligned;")
#define TC_COMMIT(a)      asm volatile("tcgen05.commit.cta_group::1.mbarrier::arrive::one.shared::cluster.b64 [%0];" :: "r"(a) : "memory")
#define TC_WAIT_LD()      asm volatile("tcgen05.wait::ld.sync.aligned;" ::: "memory")
#define TC_WAIT_ST()      asm volatile("tcgen05.wait::st.sync.aligned;" ::: "memory")
#define TC_FENCE_BEFORE() asm volatile("tcgen05.fence::before_thread_sync;" ::: "memory")
#define TC_FENCE_AFTER()  asm volatile("tcgen05.fence::after_thread_sync;" ::: "memory")
#define FENCE_ASYNC()     asm volatile("fence.proxy.async.shared::cta;" ::: "memory")

#define TC_LD_X32(r, ta) \
    asm volatile("tcgen05.ld.sync.aligned.32x32b.x32.b32 " \
        "{%0,%1,%2,%3,%4,%5,%6,%7,%8,%9,%10,%11,%12,%13,%14,%15," \
        "%16,%17,%18,%19,%20,%21,%22,%23,%24,%25,%26,%27,%28,%29,%30,%31}, [%32];" \
        : "=r"((r)[0]),"=r"((r)[1]),"=r"((r)[2]),"=r"((r)[3]),"=r"((r)[4]),"=r"((r)[5]),"=r"((r)[6]),"=r"((r)[7]), \
          "=r"((r)[8]),"=r"((r)[9]),"=r"((r)[10]),"=r"((r)[11]),"=r"((r)[12]),"=r"((r)[13]),"=r"((r)[14]),"=r"((r)[15]), \
          "=r"((r)[16]),"=r"((r)[17]),"=r"((r)[18]),"=r"((r)[19]),"=r"((r)[20]),"=r"((r)[21]),"=r"((r)[22]),"=r"((r)[23]), \
          "=r"((r)[24]),"=r"((r)[25]),"=r"((r)[26]),"=r"((r)[27]),"=r"((r)[28]),"=r"((r)[29]),"=r"((r)[30]),"=r"((r)[31]) \
        : "r"(ta))

#define TC_ST_X16(ta, r) \
    asm volatile("tcgen05.st.sync.aligned.32x32b.x16.b32 [%0], " \
        "{%1,%2,%3,%4,%5,%6,%7,%8,%9,%10,%11,%12,%13,%14,%15,%16};" \
        :: "r"(ta), \
           "r"((r)[0]),"r"((r)[1]),"r"((r)[2]),"r"((r)[3]),"r"((r)[4]),"r"((r)[5]),"r"((r)[6]),"r"((r)[7]), \
           "r"((r)[8]),"r"((r)[9]),"r"((r)[10]),"r"((r)[11]),"r"((r)[12]),"r"((r)[13]),"r"((r)[14]),"r"((r)[15]) \
        : "memory")

__device__ __forceinline__ void mma_ss(uint32_t d, uint64_t a, uint64_t b, uint32_t idesc, uint32_t en) {
    asm volatile("{\n\t.reg .pred p;\n\tsetp.ne.u32 p, %5, 0;\n\t"
        "tcgen05.mma.cta_group::1.kind::f16 [%0], %1, %2, %3, {%4,%4,%4,%4}, p;\n\t}"
        :: "r"(d), "l"(a), "l"(b), "r"(idesc), "r"(0u), "r"(en) : "memory");
}
__device__ __forceinline__ void mma_ts(uint32_t d, uint32_t a, uint64_t b, uint32_t idesc, uint32_t en) {
    asm volatile("{\n\t.reg .pred p;\n\tsetp.ne.u32 p, %5, 0;\n\t"
        "tcgen05.mma.cta_group::1.kind::f16 [%0], [%1], %2, %3, {%4,%4,%4,%4}, p;\n\t}"
        :: "r"(d), "r"(a), "l"(b), "r"(idesc), "r"(0u), "r"(en) : "memory");
}

// blocked-atom SW128 byte offsets (pre-swizzle)
__device__ __forceinline__ uint32_t q_off(int r, int d) { return (uint32_t)(((r >> 3) + (d >> 6) * 16) * 1024 + (r & 7) * 128 + (d & 63) * 2); }
__device__ __forceinline__ uint32_t k_off(int j, int d) { return (uint32_t)(((j >> 3) + (d >> 6) * 8)  * 1024 + (j & 7) * 128 + (d & 63) * 2); }
__device__ __forceinline__ uint32_t v_off(int d, int j) { return (uint32_t)((d >> 3) * 1024 + (d & 7) * 128 + j * 2); }

__device__ __forceinline__ void load_k(const float* kp, int n0, char* smem, int buf, int tid2) {
    const int lane = tid2 & 31, wq = tid2 >> 5;
    char* kh = smem + OFF_K + buf * 32768;
    char* kl = kh + 16384;
    #pragma unroll 4
    for (int it = 0; it < 16; it++) {
        const int j = it * 4 + wq;
        const float4 x = *(const float4*)(kp + (size_t)(n0 + j) * DH + lane * 4);
        const uint32_t h01 = pack2(x.x, x.y), h23 = pack2(x.z, x.w);
        const uint32_t l01 = pack2(x.x - lo_f(h01), x.y - hi_f(h01));
        const uint32_t l23 = pack2(x.z - lo_f(h23), x.w - hi_f(h23));
        const uint32_t off = SWZ(k_off(j, lane * 4));
        *(uint2*)(kh + off) = make_uint2(h01, h23);
        *(uint2*)(kl + off) = make_uint2(l01, l23);
    }
}
__device__ __forceinline__ void load_v(const float* vp, int n0, char* smem, int buf, int tid2) {
    const int lane = tid2 & 31, wq = tid2 >> 5;
    char* vh = smem + OFF_V + buf * 32768;
    char* vl = vh + 16384;
    const float* va = vp + (size_t)(n0 + 2 * lane) * DH;
    const float* vb = va + DH;
    #pragma unroll 2
    for (int dg = 0; dg < 8; dg++) {
        const int d0 = wq * 32 + dg * 4;
        const float4 a = *(const float4*)(va + d0);
        const float4 b = *(const float4*)(vb + d0);
        const float av[4] = {a.x, a.y, a.z, a.w}, bv[4] = {b.x, b.y, b.z, b.w};
        #pragma unroll
        for (int i = 0; i < 4; i++) {
            const uint32_t h = pack2(av[i], bv[i]);
            const uint32_t l = pack2(av[i] - lo_f(h), bv[i] - hi_f(h));
            const uint32_t off = SWZ(v_off(d0 + i, 2 * lane));
            *(uint32_t*)(vh + off) = h;
            *(uint32_t*)(vl + off) = l;
        }
    }
}

// QK into S[sbuf] from K[kbuf]; no commit here.
__device__ __forceinline__ void issue_qk(uint32_t sb, uint32_t tb, int sbuf, int kbuf) {
    const uint32_t d = tb + TM_S0 + 64 * sbuf;
    const uint64_t qh = mk_desc(sb + OFF_QH), ql = mk_desc(sb + OFF_QL);
    const uint64_t kh = mk_desc(sb + OFF_K + kbuf * 32768), kl = kh + 1024;
    const uint64_t aa[3] = {qh, qh, ql};
    const uint64_t bb[3] = {kh, kl, kh};
    #pragma unroll
    for (int term = 0; term < 3; term++)
        #pragma unroll
        for (int s = 0; s < 8; s++)
            mma_ss(d, aa[term] + (s >> 2) * 1024 + (s & 3) * 2,
                      bb[term] + (s >> 2) * 512  + (s & 3) * 2,
                   IDESC_QK, (term == 0 && s == 0) ? 0u : 1u);
}
__device__ __forceinline__ void issue_pv(uint32_t sb, uint32_t tb, int pbuf, int vbuf, int first) {
    const uint32_t d = tb + TM_O;
    const uint64_t vh = mk_desc(sb + OFF_V + vbuf * 32768), vl = vh + 1024;
    const uint32_t pb = tb + TM_P0 + 64 * pbuf;
    const uint32_t pa[3] = {pb, pb, pb + 32};
    const uint64_t bb[3] = {vh, vl, vh};
    #pragma unroll
    for (int term = 0; term < 3; term++)
        #pragma unroll
        for (int s = 0; s < 4; s++)
            mma_ts(d, pa[term] + s * 8, bb[term] + s * 2,
                   IDESC_PV, (first && term == 0 && s == 0) ? 0u : 1u);
}
#endif  // HAS_TCGEN05

__global__ __launch_bounds__(NTH, 1)
void sink_attn(const float* __restrict__ q, const float* __restrict__ k,
               const float* __restrict__ v, const int* __restrict__ p_ns,
               const int* __restrict__ p_ws, float* __restrict__ out, int N)
{
    extern __shared__ char smem_raw[];
    const int ns = p_ns[0], ws = p_ws[0];
    const int m0 = (int)(gridDim.x - 1 - blockIdx.x) * BM;
    const size_t plane = (size_t)blockIdx.y * (size_t)N * DH;
    const float* qp = q + plane;
    const float* kp = k + plane;
    const float* vp = v + plane;
    float* op = out + plane;
    const int tid = threadIdx.x, lane = tid & 31, wid = tid >> 5;

    // tile schedule: window must cover row m0 (keys from m0-ws+1)
    int n_lo = m0 - ws + 1;
    if (n_lo < 0) n_lo = 0;
    n_lo = (n_lo / BN) * BN;
    int n_sink = 0;
    if (n_lo > 0) {
        int t = (ns + BN - 1) / BN, cap = n_lo / BN;
        n_sink = t < cap ? t : cap;
    }
    const int n_tiles = n_sink + (m0 + BM - BN - n_lo) / BN + 1;
    const float qscale = 1.4426950408889634f * 0.08838834764831845f; // log2e/sqrt(128)

#if HAS_TCGEN05
    // ================= tcgen05 body =================
    char* smem = smem_raw;
    const uint32_t sb = smem_u32(smem);

    if (wid == 0) { TC_ALLOC(sb, TMEM_COLS); TC_RELINQ(); }
    if (tid == 0) MBAR_INIT(sb + 16, 1);
    __syncthreads();
    uint32_t tb;
    asm volatile("ld.shared.b32 %0, [%1];" : "=r"(tb) : "r"(sb));

    #define N0_OF(t) (((t) < n_sink) ? (t) * BN : n_lo + ((t) - n_sink) * BN)

    // prologue: WG0 preps Q hi/lo; WG1 loads K0,V0 (buf0) and K1 (buf1)
    if (tid < 128) {
        #pragma unroll 4
        for (int it = 0; it < 32; it++) {
            const int j = it * 4 + wid;
            float4 x = *(const float4*)(qp + (size_t)(m0 + j) * DH + lane * 4);
            x.x *= qscale; x.y *= qscale; x.z *= qscale; x.w *= qscale;
            const uint32_t h01 = pack2(x.x, x.y), h23 = pack2(x.z, x.w);
            const uint32_t l01 = pack2(x.x - lo_f(h01), x.y - hi_f(h01));
            const uint32_t l23 = pack2(x.z - lo_f(h23), x.w - hi_f(h23));
            const uint32_t off = SWZ(q_off(j, lane * 4));
            *(uint2*)(smem + OFF_QH + off) = make_uint2(h01, h23);
            *(uint2*)(smem + OFF_QL + off) = make_uint2(l01, l23);
        }
    } else {
        load_k(kp, N0_OF(0), smem, 0, tid - 128);
        load_v(vp, N0_OF(0), smem, 0, tid - 128);
        if (n_tiles > 1) load_k(kp, N0_OF(1), smem, 1, tid - 128);
    }
    FENCE_ASYNC();
    __syncthreads();

    if (wid == 0) {
        TC_FENCE_AFTER();
        if (elect_one()) { issue_qk(sb, tb, 0, 0); TC_COMMIT(sb + 16); }
    }

    float lsum = 0.0f;
    for (int t = 0; t < n_tiles; t++) {
        const int n0 = N0_OF(t);
        const int buf = t & 1;

        mbar_wait(sb + 16, t & 1);   // C(t) = {QK(t), PV(t-1)} done
        TC_FENCE_AFTER();

        // dispatch QK(t+1) NOW (uncommitted) so it runs on the tensor pipe
        // during softmax(t); committed together with PV(t) below.
        if (wid == 0 && t + 1 < n_tiles) {
            if (elect_one()) issue_qk(sb, tb, (t + 1) & 1, (t + 1) & 1);
        }

        if (tid < 128) {
            const int ig = m0 + wid * 32 + lane;
            const uint32_t woff = (uint32_t)wid << 21;
            const uint32_t s_base = tb + TM_S0 + 64 * buf;
            const uint32_t p_base = tb + TM_P0 + 64 * buf;
            #pragma unroll
            for (int c = 0; c < 2; c++) {
                uint32_t sr[32];
                TC_LD_X32(sr, s_base + c * 32);
                TC_WAIT_LD();
                const int jb = n0 + c * 32;
                uint32_t ph[16], pl[16];
                float acc = 0.0f;
                #pragma unroll
                for (int kk = 0; kk < 32; kk += 2) {
                    const int j0 = jb + kk, j1 = j0 + 1;
                    float x0 = __uint_as_float(sr[kk]);
                    float x1 = __uint_as_float(sr[kk + 1]);
                    if (!((j0 <= ig) && ((j0 < ns) | ((ig - j0) < ws)))) x0 = -126.0f;
                    if (!((j1 <= ig) && ((j1 < ns) | ((ig - j1) < ws)))) x1 = -126.0f;
                    const float p0 = ex2f(x0), p1 = ex2f(x1);
                    acc += p0 + p1;
                    const uint32_t h = pack2(p0, p1);
                    ph[kk >> 1] = h;
                    pl[kk >> 1] = pack2(p0 - lo_f(h), p1 - hi_f(h));
                }
                lsum += acc;
                TC_ST_X16(p_base + c * 16 + woff, ph);
                TC_ST_X16(p_base + 32 + c * 16 + woff, pl);
            }
            TC_WAIT_ST();
            TC_FENCE_BEFORE();
        } else {
            // loader: K two ahead (into buf t&1), V one ahead (into buf (t+1)&1)
            if (t + 2 < n_tiles) load_k(kp, N0_OF(t + 2), smem, buf, tid - 128);
            if (t + 1 < n_tiles) load_v(vp, N0_OF(t + 1), smem, (t + 1) & 1, tid - 128);
            FENCE_ASYNC();
        }
        __syncthreads();

        if (wid == 0) {
            TC_FENCE_AFTER();
            if (elect_one()) {
                issue_pv(sb, tb, buf, buf, t == 0);
                TC_COMMIT(sb + 16);   // C(t+1) = {QK(t+1), PV(t)}
            }
        }
    }

    mbar_wait(sb + 16, n_tiles & 1);   // final PV done
    TC_FENCE_AFTER();

    if (tid < 128) {
        const float inv = 1.0f / lsum;
        float* orow = op + (size_t)(m0 + wid * 32 + lane) * DH;
        #pragma unroll
        for (int c = 0; c < 4; c++) {
            uint32_t orr[32];
            TC_LD_X32(orr, tb + TM_O + c * 32);
            TC_WAIT_LD();
            float4* dst = (float4*)(orow + c * 32);
            #pragma unroll
            for (int g = 0; g < 8; g++)
                dst[g] = make_float4(__uint_as_float(orr[4 * g + 0]) * inv,
                                     __uint_as_float(orr[4 * g + 1]) * inv,
                                     __uint_as_float(orr[4 * g + 2]) * inv,
                                     __uint_as_float(orr[4 * g + 3]) * inv);
        }
        TC_FENCE_BEFORE();
    }
    __syncthreads();
    if (wid == 0) TC_DEALLOC(tb, TMEM_COLS);

#else
    // ================= SIMT fallback (proven R3 body) =================
    float* smemf = (float*)smem_raw;
    float* Qt = smemf;
    float* Kt = Qt + DH * QT_STRIDE;
    float* Vs = Kt + DH * KT_STRIDE;
    float* Ps = Vs + BN * DH;

    const int warp = wid;
    const int tx  = tid & 15;
    const int tyg = tid >> 4;

    {
        const int u = lane & 3, g = lane >> 2;
        #pragma unroll
        for (int half = 0; half < 2; half++) {
            const int row = half * 64 + warp * 8 + g;
            const float4* src = (const float4*)(qp + (size_t)(m0 + row) * DH);
            #pragma unroll
            for (int it = 0; it < 8; it++) {
                const int c4 = it * 4 + u;
                float4 val = src[c4];
                float* dst = Qt + (4 * c4) * QT_STRIDE + row;
                dst[0 * QT_STRIDE] = val.x * qscale;
                dst[1 * QT_STRIDE] = val.y * qscale;
                dst[2 * QT_STRIDE] = val.z * qscale;
                dst[3 * QT_STRIDE] = val.w * qscale;
            }
        }
    }

    float O[8][8], mrow[8], lrow[8];
    #pragma unroll
    for (int i = 0; i < 8; i++) {
        mrow[i] = -1e30f; lrow[i] = 0.0f;
        #pragma unroll
        for (int c = 0; c < 8; c++) O[i][c] = 0.0f;
    }

    const int ibase = m0 + 8 * tyg;
    const int jbase0 = 4 * tx;

    for (int t = 0; t < n_tiles; t++) {
        const int n0 = (t < n_sink) ? t * BN : n_lo + (t - n_sink) * BN;
        __syncthreads();
        {
            const int u = lane & 3, g = lane >> 2;
            const int row = warp * 8 + g;
            const float4* src = (const float4*)(kp + (size_t)(n0 + row) * DH);
            #pragma unroll
            for (int it = 0; it < 8; it++) {
                const int c4 = it * 4 + u;
                float4 val = src[c4];
                float* dst = Kt + (4 * c4) * KT_STRIDE + row;
                dst[0 * KT_STRIDE] = val.x;
                dst[1 * KT_STRIDE] = val.y;
                dst[2 * KT_STRIDE] = val.z;
                dst[3 * KT_STRIDE] = val.w;
            }
        }
        {
            const float4* src = (const float4*)(vp + (size_t)n0 * DH);
            float4* dst = (float4*)Vs;
            #pragma unroll
            for (int it = 0; it < 8; it++) dst[it * NTH + tid] = src[it * NTH + tid];
        }
        __syncthreads();

        float s[8][4];
        #pragma unroll
        for (int i = 0; i < 8; i++)
            #pragma unroll
            for (int j = 0; j < 4; j++) s[i][j] = 0.0f;

        #pragma unroll 2
        for (int kk = 0; kk < DH; kk++) {
            const float4* qrow = (const float4*)(Qt + kk * QT_STRIDE);
            const float4* krow = (const float4*)(Kt + kk * KT_STRIDE);
            float4 q0 = qrow[2 * tyg], q1 = qrow[2 * tyg + 1], kv = krow[tx];
            float qr[8] = {q0.x, q0.y, q0.z, q0.w, q1.x, q1.y, q1.z, q1.w};
            float kr[4] = {kv.x, kv.y, kv.z, kv.w};
            #pragma unroll
            for (int i = 0; i < 8; i++)
                #pragma unroll
                for (int j = 0; j < 4; j++) s[i][j] += qr[i] * kr[j];
        }

        const int jb = n0 + jbase0;
        #pragma unroll
        for (int i = 0; i < 8; i++) {
            const int ig = ibase + i;
            #pragma unroll
            for (int j = 0; j < 4; j++) {
                const int jg = jb + j;
                if (!((jg <= ig) && ((jg < ns) | ((ig - jg) < ws)))) s[i][j] = -1e30f;
            }
            float tm = fmaxf(fmaxf(s[i][0], s[i][1]), fmaxf(s[i][2], s[i][3]));
            #pragma unroll
            for (int off = 8; off > 0; off >>= 1)
                tm = fmaxf(tm, __shfl_xor_sync(0xffffffffu, tm, off));
            const float mnew = fmaxf(mrow[i], tm);
            const float alpha = ex2f(mrow[i] - mnew);
            mrow[i] = mnew;
            float rs = 0.0f;
            #pragma unroll
            for (int j = 0; j < 4; j++) { const float p = ex2f(s[i][j] - mnew); s[i][j] = p; rs += p; }
            #pragma unroll
            for (int off = 8; off > 0; off >>= 1)
                rs += __shfl_xor_sync(0xffffffffu, rs, off);
            lrow[i] = lrow[i] * alpha + rs;
            #pragma unroll
            for (int c = 0; c < 8; c++) O[i][c] *= alpha;
            ((float4*)(Ps + (8 * tyg + i) * PS_STRIDE))[tx] =
                make_float4(s[i][0], s[i][1], s[i][2], s[i][3]);
        }
        __syncthreads();

        #pragma unroll 2
        for (int j = 0; j < BN; j++) {
            const float4* vrow = (const float4*)(Vs + j * DH);
            const float4 v0 = vrow[tx], v1 = vrow[16 + tx];
            float pr[8];
            #pragma unroll
            for (int i = 0; i < 8; i++) pr[i] = Ps[(8 * tyg + i) * PS_STRIDE + j];
            #pragma unroll
            for (int i = 0; i < 8; i++) {
                O[i][0] += pr[i] * v0.x; O[i][1] += pr[i] * v0.y;
                O[i][2] += pr[i] * v0.z; O[i][3] += pr[i] * v0.w;
                O[i][4] += pr[i] * v1.x; O[i][5] += pr[i] * v1.y;
                O[i][6] += pr[i] * v1.z; O[i][7] += pr[i] * v1.w;
            }
        }
    }

    #pragma unroll
    for (int i = 0; i < 8; i++) {
        const float linv = 1.0f / lrow[i];
        float* orow = op + (size_t)(ibase + i) * DH;
        ((float4*)orow)[tx] = make_float4(O[i][0]*linv, O[i][1]*linv, O[i][2]*linv, O[i][3]*linv);
        ((float4*)orow)[16 + tx] = make_float4(O[i][4]*linv, O[i][5]*linv, O[i][6]*linv, O[i][7]*linv);
    }
#endif
}

extern "C" void kernel_launch(void* const* d_in, const int* in_sizes, int n_in,
                              void* d_out, int out_size) {
    const float* q = (const float*)d_in[0];
    const float* k = (const float*)d_in[1];
    const float* v = (const float*)d_in[2];
    const int* ns  = (const int*)d_in[3];
    const int* ws  = (const int*)d_in[4];
    float* out = (float*)d_out;

    const int N = 2048;
    const int BH = in_sizes[0] / (N * DH);

    cudaFuncSetAttribute(sink_attn,
                         cudaFuncAttributeMaxDynamicSharedMemorySize, SMEM_TOTAL);
    dim3 grid(N / BM, BH);
    sink_attn<<<grid, NTH, SMEM_TOTAL>>>(q, k, v, ns, ws, out, N);
}

// round 16
// speedup vs baseline: 5.4850x; 1.1057x over previous
#include <cuda_runtime.h>
#include <cuda_bf16.h>
#include <cstdint>

#define BM 128
#define BN 64
#define DH 128
#define NTH 256

#define OFF_QH 1024
#define OFF_QL (OFF_QH + 32768)
#define OFF_K  (OFF_QL + 32768)   /* + buf*32768, lo half at +16384 */
#define OFF_V  (OFF_K + 65536)    /* + buf*32768, lo half at +16384 */
#define SMEM_TOTAL (OFF_V + 65536)

#define QT_STRIDE (BM + 4)
#define KT_STRIDE (BN + 4)
#define PS_STRIDE (BN + 4)

// TMEM: O[0,128) | S0[128,192) S1[192,256) | P0 h/l [256,320) P1 h/l [320,384)
#define TM_O   0
#define TM_S0  128
#define TM_P0  256
#define TMEM_COLS 512

#define IDESC_QK 0x8100490u
#define IDESC_PV 0x8200490u

#define SWZ(x) ((x) ^ (((x) >> 3) & 0x70))

#if defined(__CUDA_ARCH_FEAT_SM103_ALL) || defined(__CUDA_ARCH_FEAT_SM100_ALL) || \
    (defined(__CUDA_ARCH_SPECIFIC__) && (__CUDA_ARCH_SPECIFIC__ >= 1000)) || \
    (defined(__CUDA_ARCH_FAMILY_SPECIFIC__) && (__CUDA_ARCH_FAMILY_SPECIFIC__ >= 1000))
#define HAS_TCGEN05 1
#else
#define HAS_TCGEN05 0
#endif

__device__ __forceinline__ float ex2f(float x) {
    float y; asm("ex2.approx.ftz.f32 %0, %1;" : "=f"(y) : "f"(x)); return y;
}

#if HAS_TCGEN05
static constexpr uint64_t DESC_BASE =
    (2ull << 61) | (1ull << 46) | (64ull << 32) | (1ull << 16);
__device__ __forceinline__ uint64_t mk_desc(uint32_t a) {
    return DESC_BASE | ((uint64_t)(a >> 4) & 0x3FFF);
}
__device__ __forceinline__ uint32_t smem_u32(const void* p) {
    uint32_t a;
    asm("{ .reg .u64 t; cvta.to.shared.u64 t, %1; cvt.u32.u64 %0, t; }" : "=r"(a) : "l"(p));
    return a;
}
__device__ __forceinline__ uint32_t elect_one() {
    uint32_t pr;
    asm volatile("{\n\t.reg .pred p;\n\telect.sync _|p, 0xFFFFFFFF;\n\tselp.b32 %0, 1, 0, p;\n\t}" : "=r"(pr));
    return pr;
}
__device__ __forceinline__ uint32_t pack2(float a, float b) {  // lo=a, hi=b
    uint32_t r; asm("cvt.rn.bf16x2.f32 %0, %1, %2;" : "=r"(r) : "f"(b), "f"(a)); return r;
}
__device__ __forceinline__ float lo_f(uint32_t u) { return __uint_as_float(u << 16); }
__device__ __forceinline__ float hi_f(uint32_t u) { return __uint_as_float(u & 0xffff0000u); }

#define MBAR_INIT(a, c) asm volatile("mbarrier.init.shared.b64 [%0], %1;" :: "r"(a), "r"(c) : "memory")

// Bounded wait: protocol hang -> wrong output (diagnosable), not timeout.
__device__ __forceinline__ void mbar_wait(uint32_t a, uint32_t ph) {
    for (int i = 0; i < (1 << 22); i++) {
        uint32_t done;
        asm volatile("{\n\t.reg .pred P;\n\t"
            "mbarrier.try_wait.parity.acquire.cta.shared::cta.b64 P, [%1], %2, 0x989680;\n\t"
            "selp.b32 %0, 1, 0, P;\n\t}"
            : "=r"(done) : "r"(a), "r"(ph) : "memory");
        if (done) return;
    }
}

#define TC_ALLOC(sa, n)   asm volatile("tcgen05.alloc.cta_group::1.sync.aligned.shared::cta.b32 [%0], %1;" :: "r"(sa), "r"(n) : "memory")
#define TC_DEALLOC(tb, n) asm volatile("tcgen05.dealloc.cta_group::1.sync.aligned.b32 %0, %1;" :: "r"(tb), "r"(n))
#define TC_RELINQ()       asm volatile("tcgen05.relinquish_alloc_permit.cta_group::1.sync.aligned;")
#define TC_COMMIT(a)      asm volatile("tcgen05.commit.cta_group::1.mbarrier::arrive::one.shared::cluster.b64 [%0];" :: "r"(a) : "memory")
#define TC_WAIT_LD()      asm volatile("tcgen05.wait::ld.sync.aligned;" ::: "memory")
#define TC_WAIT_ST()      asm volatile("tcgen05.wait::st.sync.aligned;" ::: "memory")
#define TC_FENCE_BEFORE() asm volatile("tcgen05.fence::before_thread_sync;" ::: "memory")
#define TC_FENCE_AFTER()  asm volatile("tcgen05.fence::after_thread_sync;" ::: "memory")
#define FENCE_ASYNC()     asm volatile("fence.proxy.async.shared::cta;" ::: "memory")

#define TC_LD_X32(r, ta) \
    asm volatile("tcgen05.ld.sync.aligned.32x32b.x32.b32 " \
        "{%0,%1,%2,%3,%4,%5,%6,%7,%8,%9,%10,%11,%12,%13,%14,%15," \
        "%16,%17,%18,%19,%20,%21,%22,%23,%24,%25,%26,%27,%28,%29,%30,%31}, [%32];" \
        : "=r"((r)[0]),"=r"((r)[1]),"=r"((r)[2]),"=r"((r)[3]),"=r"((r)[4]),"=r"((r)[5]),"=r"((r)[6]),"=r"((r)[7]), \
          "=r"((r)[8]),"=r"((r)[9]),"=r"((r)[10]),"=r"((r)[11]),"=r"((r)[12]),"=r"((r)[13]),"=r"((r)[14]),"=r"((r)[15]), \
          "=r"((r)[16]),"=r"((r)[17]),"=r"((r)[18]),"=r"((r)[19]),"=r"((r)[20]),"=r"((r)[21]),"=r"((r)[22]),"=r"((r)[23]), \
          "=r"((r)[24]),"=r"((r)[25]),"=r"((r)[26]),"=r"((r)[27]),"=r"((r)[28]),"=r"((r)[29]),"=r"((r)[30]),"=r"((r)[31]) \
        : "r"(ta))

#define TC_ST_X16(ta, r) \
    asm volatile("tcgen05.st.sync.aligned.32x32b.x16.b32 [%0], " \
        "{%1,%2,%3,%4,%5,%6,%7,%8,%9,%10,%11,%12,%13,%14,%15,%16};" \
        :: "r"(ta), \
           "r"((r)[0]),"r"((r)[1]),"r"((r)[2]),"r"((r)[3]),"r"((r)[4]),"r"((r)[5]),"r"((r)[6]),"r"((r)[7]), \
           "r"((r)[8]),"r"((r)[9]),"r"((r)[10]),"r"((r)[11]),"r"((r)[12]),"r"((r)[13]),"r"((r)[14]),"r"((r)[15]) \
        : "memory")

__device__ __forceinline__ void mma_ss(uint32_t d, uint64_t a, uint64_t b, uint32_t idesc, uint32_t en) {
    asm volatile("{\n\t.reg .pred p;\n\tsetp.ne.u32 p, %5, 0;\n\t"
        "tcgen05.mma.cta_group::1.kind::f16 [%0], %1, %2, %3, {%4,%4,%4,%4}, p;\n\t}"
        :: "r"(d), "l"(a), "l"(b), "r"(idesc), "r"(0u), "r"(en) : "memory");
}
__device__ __forceinline__ void mma_ts(uint32_t d, uint32_t a, uint64_t b, uint32_t idesc, uint32_t en) {
    asm volatile("{\n\t.reg .pred p;\n\tsetp.ne.u32 p, %5, 0;\n\t"
        "tcgen05.mma.cta_group::1.kind::f16 [%0], [%1], %2, %3, {%4,%4,%4,%4}, p;\n\t}"
        :: "r"(d), "r"(a), "l"(b), "r"(idesc), "r"(0u), "r"(en) : "memory");
}

__device__ __forceinline__ uint32_t q_off(int r, int d) { return (uint32_t)(((r >> 3) + (d >> 6) * 16) * 1024 + (r & 7) * 128 + (d & 63) * 2); }
__device__ __forceinline__ uint32_t k_off(int j, int d) { return (uint32_t)(((j >> 3) + (d >> 6) * 8)  * 1024 + (j & 7) * 128 + (d & 63) * 2); }
__device__ __forceinline__ uint32_t v_off(int d, int j) { return (uint32_t)((d >> 3) * 1024 + (d & 7) * 128 + j * 2); }

// 128-thread loaders (prologue)
__device__ __forceinline__ void load_k128(const float* kp, int n0, char* smem, int buf, int tid2) {
    const int lane = tid2 & 31, wq = tid2 >> 5;
    char* kh = smem + OFF_K + buf * 32768;
    char* kl = kh + 16384;
    #pragma unroll 4
    for (int it = 0; it < 16; it++) {
        const int j = it * 4 + wq;
        const float4 x = *(const float4*)(kp + (size_t)(n0 + j) * DH + lane * 4);
        const uint32_t h01 = pack2(x.x, x.y), h23 = pack2(x.z, x.w);
        const uint32_t l01 = pack2(x.x - lo_f(h01), x.y - hi_f(h01));
        const uint32_t l23 = pack2(x.z - lo_f(h23), x.w - hi_f(h23));
        const uint32_t off = SWZ(k_off(j, lane * 4));
        *(uint2*)(kh + off) = make_uint2(h01, h23);
        *(uint2*)(kl + off) = make_uint2(l01, l23);
    }
}
__device__ __forceinline__ void load_v128(const float* vp, int n0, char* smem, int buf, int tid2) {
    const int lane = tid2 & 31, wq = tid2 >> 5;
    char* vh = smem + OFF_V + buf * 32768;
    char* vl = vh + 16384;
    const float* va = vp + (size_t)(n0 + 2 * lane) * DH;
    const float* vb = va + DH;
    #pragma unroll 2
    for (int dg = 0; dg < 8; dg++) {
        const int d0 = wq * 32 + dg * 4;
        const float4 a = *(const float4*)(va + d0);
        const float4 b = *(const float4*)(vb + d0);
        const float av[4] = {a.x, a.y, a.z, a.w}, bv[4] = {b.x, b.y, b.z, b.w};
        #pragma unroll
        for (int i = 0; i < 4; i++) {
            const uint32_t h = pack2(av[i], bv[i]);
            const uint32_t l = pack2(av[i] - lo_f(h), bv[i] - hi_f(h));
            const uint32_t off = SWZ(v_off(d0 + i, 2 * lane));
            *(uint32_t*)(vh + off) = h;
            *(uint32_t*)(vl + off) = l;
        }
    }
}
// 256-thread loaders (mainloop)
__device__ __forceinline__ void load_k256(const float* kp, int n0, char* smem, int buf, int tid) {
    const int lane = tid & 31, wq = tid >> 5;
    char* kh = smem + OFF_K + buf * 32768;
    char* kl = kh + 16384;
    #pragma unroll 4
    for (int it = 0; it < 8; it++) {
        const int j = it * 8 + wq;
        const float4 x = *(const float4*)(kp + (size_t)(n0 + j) * DH + lane * 4);
        const uint32_t h01 = pack2(x.x, x.y), h23 = pack2(x.z, x.w);
        const uint32_t l01 = pack2(x.x - lo_f(h01), x.y - hi_f(h01));
        const uint32_t l23 = pack2(x.z - lo_f(h23), x.w - hi_f(h23));
        const uint32_t off = SWZ(k_off(j, lane * 4));
        *(uint2*)(kh + off) = make_uint2(h01, h23);
        *(uint2*)(kl + off) = make_uint2(l01, l23);
    }
}
__device__ __forceinline__ void load_v256(const float* vp, int n0, char* smem, int buf, int tid) {
    const int lane = tid & 31, wq = tid >> 5;
    char* vh = smem + OFF_V + buf * 32768;
    char* vl = vh + 16384;
    const float* va = vp + (size_t)(n0 + 2 * lane) * DH;
    const float* vb = va + DH;
    #pragma unroll 2
    for (int dg = 0; dg < 4; dg++) {
        const int d0 = wq * 16 + dg * 4;
        const float4 a = *(const float4*)(va + d0);
        const float4 b = *(const float4*)(vb + d0);
        const float av[4] = {a.x, a.y, a.z, a.w}, bv[4] = {b.x, b.y, b.z, b.w};
        #pragma unroll
        for (int i = 0; i < 4; i++) {
            const uint32_t h = pack2(av[i], bv[i]);
            const uint32_t l = pack2(av[i] - lo_f(h), bv[i] - hi_f(h));
            const uint32_t off = SWZ(v_off(d0 + i, 2 * lane));
            *(uint32_t*)(vh + off) = h;
            *(uint32_t*)(vl + off) = l;
        }
    }
}

__device__ __forceinline__ void issue_qk(uint32_t sb, uint32_t tb, int sbuf, int kbuf) {
    const uint32_t d = tb + TM_S0 + 64 * sbuf;
    const uint64_t qh = mk_desc(sb + OFF_QH), ql = mk_desc(sb + OFF_QL);
    const uint64_t kh = mk_desc(sb + OFF_K + kbuf * 32768), kl = kh + 1024;
    const uint64_t aa[3] = {qh, qh, ql};
    const uint64_t bb[3] = {kh, kl, kh};
    #pragma unroll
    for (int term = 0; term < 3; term++)
        #pragma unroll
        for (int s = 0; s < 8; s++)
            mma_ss(d, aa[term] + (s >> 2) * 1024 + (s & 3) * 2,
                      bb[term] + (s >> 2) * 512  + (s & 3) * 2,
                   IDESC_QK, (term == 0 && s == 0) ? 0u : 1u);
}
__device__ __forceinline__ void issue_pv(uint32_t sb, uint32_t tb, int pbuf, int vbuf, int first) {
    const uint32_t d = tb + TM_O;
    const uint64_t vh = mk_desc(sb + OFF_V + vbuf * 32768), vl = vh + 1024;
    const uint32_t pb = tb + TM_P0 + 64 * pbuf;
    const uint32_t pa[3] = {pb, pb, pb + 32};
    const uint64_t bb[3] = {vh, vl, vh};
    #pragma unroll
    for (int term = 0; term < 3; term++)
        #pragma unroll
        for (int s = 0; s < 4; s++)
            mma_ts(d, pa[term] + s * 8, bb[term] + s * 2,
                   IDESC_PV, (first && term == 0 && s == 0) ? 0u : 1u);
}
#endif  // HAS_TCGEN05

__global__ __launch_bounds__(NTH, 1)
void sink_attn(const float* __restrict__ q, const float* __restrict__ k,
               const float* __restrict__ v, const int* __restrict__ p_ns,
               const int* __restrict__ p_ws, float* __restrict__ out, int N)
{
    extern __shared__ char smem_raw[];
    const int ns = p_ns[0], ws = p_ws[0];
    const int m0 = (int)(gridDim.x - 1 - blockIdx.x) * BM;
    const size_t plane = (size_t)blockIdx.y * (size_t)N * DH;
    const float* qp = q + plane;
    const float* kp = k + plane;
    const float* vp = v + plane;
    float* op = out + plane;
    const int tid = threadIdx.x, lane = tid & 31, wid = tid >> 5;

    int n_lo = m0 - ws + 1;
    if (n_lo < 0) n_lo = 0;
    n_lo = (n_lo / BN) * BN;
    int n_sink = 0;
    if (n_lo > 0) {
        int t = (ns + BN - 1) / BN, cap = n_lo / BN;
        n_sink = t < cap ? t : cap;
    }
    const int n_tiles = n_sink + (m0 + BM - BN - n_lo) / BN + 1;
    const float qscale = 1.4426950408889634f * 0.08838834764831845f;

#if HAS_TCGEN05
    char* smem = smem_raw;
    const uint32_t sb = smem_u32(smem);
    const uint32_t mbA = sb + 16, mbB = sb + 24;

    if (wid == 0) { TC_ALLOC(sb, TMEM_COLS); TC_RELINQ(); }
    if (tid == 0) { MBAR_INIT(mbA, 1); MBAR_INIT(mbB, 1); }
    __syncthreads();
    uint32_t tb;
    asm volatile("ld.shared.b32 %0, [%1];" : "=r"(tb) : "r"(sb));

    #define N0_OF(t) (((t) < n_sink) ? (t) * BN : n_lo + ((t) - n_sink) * BN)

    // prologue: WG0 preps Q hi/lo; WG1 loads K0,V0 (buf0), K1 (buf1)
    if (tid < 128) {
        #pragma unroll 4
        for (int it = 0; it < 32; it++) {
            const int j = it * 4 + wid;
            float4 x = *(const float4*)(qp + (size_t)(m0 + j) * DH + lane * 4);
            x.x *= qscale; x.y *= qscale; x.z *= qscale; x.w *= qscale;
            const uint32_t h01 = pack2(x.x, x.y), h23 = pack2(x.z, x.w);
            const uint32_t l01 = pack2(x.x - lo_f(h01), x.y - hi_f(h01));
            const uint32_t l23 = pack2(x.z - lo_f(h23), x.w - hi_f(h23));
            const uint32_t off = SWZ(q_off(j, lane * 4));
            *(uint2*)(smem + OFF_QH + off) = make_uint2(h01, h23);
            *(uint2*)(smem + OFF_QL + off) = make_uint2(l01, l23);
        }
    } else {
        load_k128(kp, N0_OF(0), smem, 0, tid - 128);
        load_v128(vp, N0_OF(0), smem, 0, tid - 128);
        if (n_tiles > 1) load_k128(kp, N0_OF(1), smem, 1, tid - 128);
    }
    FENCE_ASYNC();
    __syncthreads();

    if (wid == 0) {
        TC_FENCE_AFTER();
        if (elect_one()) { issue_qk(sb, tb, 0, 0); TC_COMMIT(mbA); }  // A#1: QK(0)
    }

    // softmax coords: row = (wid&3)*32+lane; column half by warpgroup
    const int colhalf = (tid >= 128) ? 1 : 0;
    const int row = (wid & 3) * 32 + lane;
    const int ig = m0 + row;
    const uint32_t woff = (uint32_t)(wid & 3) << 21;
    float lpart = 0.0f;

    for (int t = 0; t < n_tiles; t++) {
        const int n0 = N0_OF(t);
        const int buf = t & 1;

        // A#(t+1) covers QK(t) and (FIFO) PV(t-2): S[buf] readable, P[buf] writable.
        mbar_wait(mbA, t & 1);
        TC_FENCE_AFTER();

        // dispatch QK(t+1) now; commit A immediately (does NOT wait on PV(t)).
        if (wid == 0 && t + 1 < n_tiles) {
            if (elect_one()) { issue_qk(sb, tb, (t + 1) & 1, (t + 1) & 1); TC_COMMIT(mbA); }
        }

        // softmax: all 8 warps; each warp 32 rows x 32 cols
        {
            const uint32_t s_base = tb + TM_S0 + 64 * buf + colhalf * 32;
            const uint32_t p_base = tb + TM_P0 + 64 * buf;
            uint32_t sr[32];
            TC_LD_X32(sr, s_base);
            TC_WAIT_LD();
            const int jb = n0 + colhalf * 32;
            uint32_t ph[16], pl[16];
            float acc = 0.0f;
            #pragma unroll
            for (int kk = 0; kk < 32; kk += 2) {
                const int j0 = jb + kk, j1 = j0 + 1;
                float x0 = __uint_as_float(sr[kk]);
                float x1 = __uint_as_float(sr[kk + 1]);
                if (!((j0 <= ig) && ((j0 < ns) | ((ig - j0) < ws)))) x0 = -126.0f;
                if (!((j1 <= ig) && ((j1 < ns) | ((ig - j1) < ws)))) x1 = -126.0f;
                const float p0 = ex2f(x0), p1 = ex2f(x1);
                acc += p0 + p1;
                const uint32_t h = pack2(p0, p1);
                ph[kk >> 1] = h;
                pl[kk >> 1] = pack2(p0 - lo_f(h), p1 - hi_f(h));
            }
            lpart += acc;
            TC_ST_X16(p_base + colhalf * 16 + woff, ph);
            TC_ST_X16(p_base + 32 + colhalf * 16 + woff, pl);
            TC_WAIT_ST();
            TC_FENCE_BEFORE();
        }

        // loads on all 256 threads. K needs only wait A (QK(t) done).
        if (t + 2 < n_tiles) load_k256(kp, N0_OF(t + 2), smem, buf, tid);
        if (t + 1 < n_tiles) {
            if (t >= 1) mbar_wait(mbB, (t - 1) & 1);  // PV(t-1) done -> V[(t+1)&1] free
            load_v256(vp, N0_OF(t + 1), smem, (t + 1) & 1, tid);
        }
        FENCE_ASYNC();
        __syncthreads();

        if (wid == 0) {
            TC_FENCE_AFTER();
            if (elect_one()) { issue_pv(sb, tb, buf, buf, t == 0); TC_COMMIT(mbB); }  // B#(t+1)
        }
    }

    mbar_wait(mbB, (n_tiles - 1) & 1);   // final PV done
    TC_FENCE_AFTER();

    // combine row-sum partials via smem (Q region is dead now)
    float* part = (float*)(smem + OFF_QH);
    part[colhalf * 128 + row] = lpart;
    __syncthreads();
    const float inv = 1.0f / (part[row] + part[128 + row]);

    // O readback: warp w covers its subpartition's rows, cols colhalf*64..+63
    // (warps w and w+4 share rows and split columns -> full 128x128 coverage)
    {
        const int cb = colhalf * 64;
        #pragma unroll
        for (int c = 0; c < 2; c++) {
            uint32_t orr[32];
            TC_LD_X32(orr, tb + TM_O + cb + c * 32);
            TC_WAIT_LD();
            float4* dst = (float4*)(op + (size_t)(m0 + row) * DH + cb + c * 32);
            #pragma unroll
            for (int g = 0; g < 8; g++)
                dst[g] = make_float4(__uint_as_float(orr[4 * g + 0]) * inv,
                                     __uint_as_float(orr[4 * g + 1]) * inv,
                                     __uint_as_float(orr[4 * g + 2]) * inv,
                                     __uint_as_float(orr[4 * g + 3]) * inv);
        }
        TC_FENCE_BEFORE();
    }
    __syncthreads();
    if (wid == 0) TC_DEALLOC(tb, TMEM_COLS);

#else
    // ================= SIMT fallback (proven R3 body) =================
    float* smemf = (float*)smem_raw;
    float* Qt = smemf;
    float* Kt = Qt + DH * QT_STRIDE;
    float* Vs = Kt + DH * KT_STRIDE;
    float* Ps = Vs + BN * DH;

    const int warp = wid;
    const int tx  = tid & 15;
    const int tyg = tid >> 4;

    {
        const int u = lane & 3, g = lane >> 2;
        #pragma unroll
        for (int half = 0; half < 2; half++) {
            const int row = half * 64 + warp * 8 + g;
            const float4* src = (const float4*)(qp + (size_t)(m0 + row) * DH);
            #pragma unroll
            for (int it = 0; it < 8; it++) {
                const int c4 = it * 4 + u;
                float4 val = src[c4];
                float* dst = Qt + (4 * c4) * QT_STRIDE + row;
                dst[0 * QT_STRIDE] = val.x * qscale;
                dst[1 * QT_STRIDE] = val.y * qscale;
                dst[2 * QT_STRIDE] = val.z * qscale;
                dst[3 * QT_STRIDE] = val.w * qscale;
            }
        }
    }

    float O[8][8], mrow[8], lrow[8];
    #pragma unroll
    for (int i = 0; i < 8; i++) {
        mrow[i] = -1e30f; lrow[i] = 0.0f;
        #pragma unroll
        for (int c = 0; c < 8; c++) O[i][c] = 0.0f;
    }

    const int ibase = m0 + 8 * tyg;
    const int jbase0 = 4 * tx;

    for (int t = 0; t < n_tiles; t++) {
        const int n0 = (t < n_sink) ? t * BN : n_lo + (t - n_sink) * BN;
        __syncthreads();
        {
            const int u = lane & 3, g = lane >> 2;
            const int row = warp * 8 + g;
            const float4* src = (const float4*)(kp + (size_t)(n0 + row) * DH);
            #pragma unroll
            for (int it = 0; it < 8; it++) {
                const int c4 = it * 4 + u;
                float4 val = src[c4];
                float* dst = Kt + (4 * c4) * KT_STRIDE + row;
                dst[0 * KT_STRIDE] = val.x;
                dst[1 * KT_STRIDE] = val.y;
                dst[2 * KT_STRIDE] = val.z;
                dst[3 * KT_STRIDE] = val.w;
            }
        }
        {
            const float4* src = (const float4*)(vp + (size_t)n0 * DH);
            float4* dst = (float4*)Vs;
            #pragma unroll
            for (int it = 0; it < 8; it++) dst[it * NTH + tid] = src[it * NTH + tid];
        }
        __syncthreads();

        float s[8][4];
        #pragma unroll
        for (int i = 0; i < 8; i++)
            #pragma unroll
            for (int j = 0; j < 4; j++) s[i][j] = 0.0f;

        #pragma unroll 2
        for (int kk = 0; kk < DH; kk++) {
            const float4* qrow = (const float4*)(Qt + kk * QT_STRIDE);
            const float4* krow = (const float4*)(Kt + kk * KT_STRIDE);
            float4 q0 = qrow[2 * tyg], q1 = qrow[2 * tyg + 1], kv = krow[tx];
            float qr[8] = {q0.x, q0.y, q0.z, q0.w, q1.x, q1.y, q1.z, q1.w};
            float kr[4] = {kv.x, kv.y, kv.z, kv.w};
            #pragma unroll
            for (int i = 0; i < 8; i++)
                #pragma unroll
                for (int j = 0; j < 4; j++) s[i][j] += qr[i] * kr[j];
        }

        const int jb = n0 + jbase0;
        #pragma unroll
        for (int i = 0; i < 8; i++) {
            const int ig = ibase + i;
            #pragma unroll
            for (int j = 0; j < 4; j++) {
                const int jg = jb + j;
                if (!((jg <= ig) && ((jg < ns) | ((ig - jg) < ws)))) s[i][j] = -1e30f;
            }
            float tm = fmaxf(fmaxf(s[i][0], s[i][1]), fmaxf(s[i][2], s[i][3]));
            #pragma unroll
            for (int off = 8; off > 0; off >>= 1)
                tm = fmaxf(tm, __shfl_xor_sync(0xffffffffu, tm, off));
            const float mnew = fmaxf(mrow[i], tm);
            const float alpha = ex2f(mrow[i] - mnew);
            mrow[i] = mnew;
            float rs = 0.0f;
            #pragma unroll
            for (int j = 0; j < 4; j++) { const float p = ex2f(s[i][j] - mnew); s[i][j] = p; rs += p; }
            #pragma unroll
            for (int off = 8; off > 0; off >>= 1)
                rs += __shfl_xor_sync(0xffffffffu, rs, off);
            lrow[i] = lrow[i] * alpha + rs;
            #pragma unroll
            for (int c = 0; c < 8; c++) O[i][c] *= alpha;
            ((float4*)(Ps + (8 * tyg + i) * PS_STRIDE))[tx] =
                make_float4(s[i][0], s[i][1], s[i][2], s[i][3]);
        }
        __syncthreads();

        #pragma unroll 2
        for (int j = 0; j < BN; j++) {
            const float4* vrow = (const float4*)(Vs + j * DH);
            const float4 v0 = vrow[tx], v1 = vrow[16 + tx];
            float pr[8];
            #pragma unroll
            for (int i = 0; i < 8; i++) pr[i] = Ps[(8 * tyg + i) * PS_STRIDE + j];
            #pragma unroll
            for (int i = 0; i < 8; i++) {
                O[i][0] += pr[i] * v0.x; O[i][1] += pr[i] * v0.y;
                O[i][2] += pr[i] * v0.z; O[i][3] += pr[i] * v0.w;
                O[i][4] += pr[i] * v1.x; O[i][5] += pr[i] * v1.y;
                O[i][6] += pr[i] * v1.z; O[i][7] += pr[i] * v1.w;
            }
        }
    }

    #pragma unroll
    for (int i = 0; i < 8; i++) {
        const float linv = 1.0f / lrow[i];
        float* orow = op + (size_t)(ibase + i) * DH;
        ((float4*)orow)[tx] = make_float4(O[i][0]*linv, O[i][1]*linv, O[i][2]*linv, O[i][3]*linv);
        ((float4*)orow)[16 + tx] = make_float4(O[i][4]*linv, O[i][5]*linv, O[i][6]*linv, O[i][7]*linv);
    }
#endif
}

extern "C" void kernel_launch(void* const* d_in, const int* in_sizes, int n_in,
                              void* d_out, int out_size) {
    const float* q = (const float*)d_in[0];
    const float* k = (const float*)d_in[1];
    const float* v = (const float*)d_in[2];
    const int* ns  = (const int*)d_in[3];
    const int* ws  = (const int*)d_in[4];
    float* out = (float*)d_out;

    const int N = 2048;
    const int BH = in_sizes[0] / (N * DH);

    cudaFuncSetAttribute(sink_attn,
                         cudaFuncAttributeMaxDynamicSharedMemorySize, SMEM_TOTAL);
    dim3 grid(N / BM, BH);
    sink_attn<<<grid, NTH, SMEM_TOTAL>>>(q, k, v, ns, ws, out, N);
}